// round 3
// baseline (speedup 1.0000x reference)
#include <cuda_runtime.h>
#include <math.h>

#define NBALLS  256
#define BATCHN  128
#define NSTEPS  100
#define MAXEV   5
#define HID     64
#define P_PAIRS 32640          // 256*255/2
#define DTCONST 0.05f
#define WORLDSZ 10.0f
#define MAXC    6144           // candidate-pair capacity
#define MAXW    512            // wall-candidate capacity
#define W2S     65             // padded W2 row stride (kills 32-way bank conflict)

// ---------------- event log scratch (device globals; no allocation) ------------
__device__ int   g_type[NSTEPS * MAXEV];
__device__ int   g_ei  [NSTEPS * MAXEV];
__device__ int   g_ej  [NSTEPS * MAXEV];
__device__ float g_dte [NSTEPS * MAXEV];
__device__ float g_dtef[NSTEPS];

__constant__ float c_wnx[4] = { 1.f, -1.f, 0.f,  0.f };
__constant__ float c_wny[4] = { 0.f,  0.f, 1.f, -1.f };
__constant__ float c_wp [4] = { 0.f, -WORLDSZ, 0.f, -WORLDSZ };

__device__ __forceinline__ float silu_f(float x) {
    float s = 1.0f / (1.0f + expf(-x));
    return x * s;
}

// monotone float -> uint mapping (order-preserving incl. negatives)
__device__ __forceinline__ unsigned fkey(float f) {
    unsigned u = __float_as_uint(f);
    return (u & 0x80000000u) ? ~u : (u | 0x80000000u);
}
__device__ __forceinline__ float funkey(unsigned u) {
    u = (u & 0x80000000u) ? (u & 0x7FFFFFFFu) : ~u;
    return __uint_as_float(u);
}

__device__ __forceinline__ int triu_off(int i) {
    return i * 255 - ((i * (i - 1)) >> 1);
}

// ---------------- candidate evaluation (identical math to the passing R1 kernel)
__device__ __forceinline__ void eval_pair(int i, int j,
    const float* px, const float* py, const float* vx, const float* vy, const float* r,
    unsigned long long& bk, unsigned& ba)
{
    float dxp = px[j] - px[i];
    float dyp = py[j] - py[i];
    float d2  = __fmaf_rn(dxp, dxp, dyp * dyp);
    if (d2 <= 0.06255f) {                              // dist <= ~0.25 (+margin)
        float dist = sqrtf(d2);
        float den  = dist + 1e-8f;
        float ab   = __fmaf_rn(vx[j] - vx[i], dxp / den, (vy[j] - vy[i]) * (dyp / den));
        if (ab < 0.0f) {
            float gap = dist - (r[i] + r[j]);
            unsigned kk = (unsigned)(triu_off(i) + (j - i - 1));
            unsigned long long key = (((unsigned long long)fkey(gap)) << 32) | kk;
            if (key < bk) { bk = key; ba = (unsigned)i; }
        }
    }
}

__device__ __forceinline__ void eval_wall(int ball, int w,
    const float* px, const float* py, const float* vx, const float* vy, const float* r,
    unsigned long long& bk)
{
    float g; bool a;
    float rr = r[ball];
    if (w == 0)      { g = px[ball] - rr;             a = vx[ball] < 0.f; }
    else if (w == 1) { g = (WORLDSZ - px[ball]) - rr; a = vx[ball] > 0.f; }
    else if (w == 2) { g = py[ball] - rr;             a = vy[ball] < 0.f; }
    else             { g = (WORLDSZ - py[ball]) - rr; a = vy[ball] > 0.f; }
    if (a) {
        unsigned long long key = (((unsigned long long)fkey(g)) << 32)
                               | (unsigned)(P_PAIRS + ball * 4 + w);
        if (key < bk) bk = key;
    }
}

// ---------------- shared apply routines ----------------------------------------
// ball-ball jump via MLP; if vmax!=nullptr (scheduler), bump *vmax by |impulse|
__device__ void apply_jump(float* px, float* py, float* vx, float* vy,
                           int i, int j,
                           const float* sW1, const float* sb1,
                           const float* sW2, const float* sb2,
                           const float* sW3, float b3v,
                           float* h1, float* h2, int tid, float* vmax)
{
    float dx = px[j] - px[i];
    float dy = py[j] - py[i];
    float dist = sqrtf(__fmaf_rn(dx, dx, dy * dy));
    dist = fmaxf(dist, 1e-8f);
    float nhx = dx / dist, nhy = dy / dist;
    float app = __fmaf_rn(vx[j] - vx[i], nhx, (vy[j] - vy[i]) * nhy);

    if (tid < HID) {
        float z = __fmaf_rn(dist, sW1[2 * tid], __fmaf_rn(app, sW1[2 * tid + 1], sb1[tid]));
        h1[tid] = silu_f(z);
    }
    __syncthreads();
    if (tid < HID) {
        float acc = 0.0f;
        const float* row = sW2 + tid * W2S;            // padded stride: conflict-free
#pragma unroll 8
        for (int m = 0; m < HID; m++) acc = __fmaf_rn(row[m], h1[m], acc);
        h2[tid] = silu_f(acc + sb2[tid]);
    }
    __syncthreads();
    if (tid == 0) {
        float acc = 0.0f;
        for (int m = 0; m < HID; m++) acc = __fmaf_rn(sW3[m], h2[m], acc);
        float imp = acc + b3v;
        float ix = imp * nhx, iy = imp * nhy;
        vx[i] += ix; vy[i] += iy;
        vx[j] -= ix; vy[j] -= iy;
        if (vmax) *vmax += fabsf(imp);
    }
    __syncthreads();
}

// wall bounce (single-thread); returns penetration correction magnitude
__device__ __forceinline__ float apply_wall1(float* px, float* py, float* vx, float* vy,
                                             int i, int w, float r)
{
    float wnx = c_wnx[w], wny = c_wny[w], wpv = c_wp[w];
    float v0 = vx[i], v1 = vy[i], p0 = px[i], p1 = py[i];
    float vn = __fmaf_rn(v0, wnx, v1 * wny);
    float t2 = 2.0f * vn;
    vx[i] = v0 - t2 * wnx;
    vy[i] = v1 - t2 * wny;
    float pn  = __fmaf_rn(p0, wnx, p1 * wny);
    float pen = fmaxf((wpv + r) - pn, 0.0f);
    px[i] = __fmaf_rn(pen, wnx, p0);
    py[i] = __fmaf_rn(pen, wny, p1);
    return pen;
}

// =============================== SCHEDULER =====================================
// One 256-thread block simulates batch 0 and emits the global event log.
// Candidate-list pruning with provably safe displacement-tracked rebuilds.
__global__ void __launch_bounds__(256, 1)
sched_kernel(const float* __restrict__ state, const float* __restrict__ radii,
             const float* __restrict__ W1, const float* __restrict__ b1,
             const float* __restrict__ W2, const float* __restrict__ b2,
             const float* __restrict__ W3, const float* __restrict__ b3)
{
    __shared__ float s_px[NBALLS], s_py[NBALLS], s_vx[NBALLS], s_vy[NBALLS], s_r[NBALLS];
    __shared__ float sW1[2 * HID], sb1[HID], sW2[HID * W2S], sb2[HID], sW3[HID];
    __shared__ float s_h1[HID], s_h2[HID];
    __shared__ unsigned long long red_k[8];
    __shared__ unsigned red_a[8];
    __shared__ float red_f[8];
    __shared__ unsigned long long s_bk;
    __shared__ unsigned s_ba;
    __shared__ int s_type, s_i, s_j, s_done, s_nc, s_nw, s_over;
    __shared__ float s_dte, s_tc, s_b3, s_disp, s_vmax;
    __shared__ unsigned short cand[MAXC];
    __shared__ unsigned short wcand[MAXW];

    const int tid  = threadIdx.x;
    const int warp = tid >> 5, lane = tid & 31;

    {   // load state: tid == ball
        float4 v = ((const float4*)state)[tid];   // batch 0 = first 256 float4s
        s_px[tid] = v.x; s_py[tid] = v.y; s_vx[tid] = v.z; s_vy[tid] = v.w;
        s_r[tid] = radii[tid];
    }
    if (tid < 2 * HID) sW1[tid] = W1[tid];
    if (tid < HID) { sb1[tid] = b1[tid]; sb2[tid] = b2[tid]; sW3[tid] = W3[tid]; }
    for (int t = tid; t < HID * HID; t += 256) sW2[(t >> 6) * W2S + (t & 63)] = W2[t];
    if (tid == 0) { s_b3 = b3[0]; s_disp = 1e30f; s_vmax = 0.f; s_over = 0; s_nc = 0; s_nw = 0; }
    __syncthreads();

    for (int step = 0; step < NSTEPS; step++) {
        float t_s = (float)step * DTCONST;
        float t_e = t_s + DTCONST;
        if (tid == 0) { s_tc = t_s; s_done = 0; }
        if (tid < MAXEV) g_type[step * MAXEV + tid] = 0;
        __syncthreads();

        for (int ev = 0; ev < MAXEV; ev++) {
            if (s_done) break;

            // -------- rebuild candidate lists when displacement bound erodes margin
            if (s_disp > 0.24f) {
                if (tid == 0) { s_nc = 0; s_nw = 0; }
                __syncthreads();
                float bx = s_px[tid], by = s_py[tid], rr = s_r[tid];
                if (bx - rr <= 0.5501f)              { int p = atomicAdd(&s_nw, 1); if (p < MAXW) wcand[p] = (unsigned short)(tid * 4 + 0); }
                if ((WORLDSZ - bx) - rr <= 0.5501f)  { int p = atomicAdd(&s_nw, 1); if (p < MAXW) wcand[p] = (unsigned short)(tid * 4 + 1); }
                if (by - rr <= 0.5501f)              { int p = atomicAdd(&s_nw, 1); if (p < MAXW) wcand[p] = (unsigned short)(tid * 4 + 2); }
                if ((WORLDSZ - by) - rr <= 0.5501f)  { int p = atomicAdd(&s_nw, 1); if (p < MAXW) wcand[p] = (unsigned short)(tid * 4 + 3); }
#pragma unroll 4
                for (int d = 1; d <= 128; d++) {
                    if (d == 128 && tid >= 128) break;
                    int o = tid + d; if (o >= 256) o -= 256;
                    float dx = s_px[o] - bx;
                    if (fabsf(dx) < 0.7502f) {
                        float dy = s_py[o] - by;
                        if (__fmaf_rn(dx, dx, dy * dy) <= 0.5628f) {   // dist <= 0.75
                            int i, j;
                            if (o > tid) { i = tid; j = o; } else { i = o; j = tid; }
                            int p = atomicAdd(&s_nc, 1);
                            if (p < MAXC) cand[p] = (unsigned short)((i << 8) | j);
                        }
                    }
                }
                // Vmax = max ball speed (displacement bound rate)
                float sp = sqrtf(__fmaf_rn(s_vx[tid], s_vx[tid], s_vy[tid] * s_vy[tid]));
#pragma unroll
                for (int off = 16; off; off >>= 1) sp = fmaxf(sp, __shfl_down_sync(0xffffffffu, sp, off));
                if (lane == 0) red_f[warp] = sp;
                __syncthreads();
                if (tid == 0) {
                    float m = red_f[0];
#pragma unroll
                    for (int k = 1; k < 8; k++) m = fmaxf(m, red_f[k]);
                    s_vmax = m;
                    s_disp = 0.0f;
                    s_over = (s_nc > MAXC) || (s_nw > MAXW);
                    if (s_nc > MAXC) s_nc = MAXC;
                    if (s_nw > MAXW) s_nw = MAXW;
                }
                __syncthreads();
            }

            // -------- detection
            unsigned long long bk = ~0ull;
            unsigned ba = 0u;
            if (!s_over) {
                int nw = s_nw, nc = s_nc;
                for (int c = tid; c < nw; c += 256) {
                    int wk = wcand[c];
                    eval_wall(wk >> 2, wk & 3, s_px, s_py, s_vx, s_vy, s_r, bk);
                }
                for (int c = tid; c < nc; c += 256) {
                    int pk = cand[c];
                    eval_pair(pk >> 8, pk & 255, s_px, s_py, s_vx, s_vy, s_r, bk, ba);
                }
            } else {
                // exact full-scan fallback
#pragma unroll
                for (int w = 0; w < 4; w++) eval_wall(tid, w, s_px, s_py, s_vx, s_vy, s_r, bk);
                float bx = s_px[tid];
                for (int d = 1; d <= 128; d++) {
                    if (d == 128 && tid >= 128) break;
                    int o = tid + d; if (o >= 256) o -= 256;
                    float dx = s_px[o] - bx;
                    if (fabsf(dx) < 0.2502f) {
                        int i, j;
                        if (o > tid) { i = tid; j = o; } else { i = o; j = tid; }
                        eval_pair(i, j, s_px, s_py, s_vx, s_vy, s_r, bk, ba);
                    }
                }
            }

            // -------- argmin reduction (8 warps); k in low bits => first-index tie-break
#pragma unroll
            for (int off = 16; off; off >>= 1) {
                unsigned long long ok = __shfl_down_sync(0xffffffffu, bk, off);
                unsigned oa = __shfl_down_sync(0xffffffffu, ba, off);
                if (ok < bk) { bk = ok; ba = oa; }
            }
            if (lane == 0) { red_k[warp] = bk; red_a[warp] = ba; }
            __syncthreads();
            if (tid == 0) {
                bk = red_k[0]; ba = red_a[0];
#pragma unroll
                for (int k = 1; k < 8; k++) {
                    if (red_k[k] < bk) { bk = red_k[k]; ba = red_a[k]; }
                }
                // -------- scalar event decision
                int type = 0, ei = 0, ej = 0;
                float dte = 0.0f;
                if (bk != ~0ull) {
                    unsigned k = (unsigned)bk;
                    float gap = funkey((unsigned)(bk >> 32));
                    if (gap <= 0.05f) {
                        bool isball = (k < P_PAIRS);
                        float app;
                        if (isball) {
                            ei = (int)ba;
                            ej = (int)k - triu_off(ei) + ei + 1;
                            float nx = s_px[ej] - s_px[ei];
                            float ny = s_py[ej] - s_py[ei];
                            float nn = sqrtf(__fmaf_rn(nx, nx, ny * ny));
                            float ax = ((s_vx[ej] - s_vx[ei]) * nx) / nn;
                            float ay = ((s_vy[ej] - s_vy[ei]) * ny) / nn;
                            app = -(ax + ay);
                        } else {
                            int kw = (int)k - P_PAIRS;
                            ei = kw >> 2; ej = kw & 3;
                            app = fabsf(fmaxf(s_vx[ei], s_vy[ei]));
                        }
                        float t_ev = s_tc + gap / fmaxf(app, 1e-6f);
                        if (gap <= 0.0f) {
                            type = isball ? 1 : 3;          // case_a
                            dte = 0.0f;
                        } else if (app > 1e-6f && t_ev < t_e) {
                            type = isball ? 2 : 4;          // case_b
                            dte = (t_ev > s_tc + 1e-10f) ? (t_ev - s_tc) : 0.0f;
                            s_tc = t_ev;
                            s_disp = __fmaf_rn(s_vmax, dte, s_disp);
                        } else {
                            s_done = 1;
                        }
                    } else s_done = 1;
                } else s_done = 1;
                s_type = type; s_i = ei; s_j = ej; s_dte = dte;
                int idx = step * MAXEV + ev;
                g_type[idx] = type; g_ei[idx] = ei; g_ej[idx] = ej; g_dte[idx] = dte;
            }
            __syncthreads();

            // -------- apply to batch-0 state
            int ty = s_type;
            if (ty != 0) {
                if (ty == 2 || ty == 4) {
                    s_px[tid] = __fmaf_rn(s_vx[tid], s_dte, s_px[tid]);
                    s_py[tid] = __fmaf_rn(s_vy[tid], s_dte, s_py[tid]);
                    __syncthreads();
                }
                if (ty <= 2) {
                    apply_jump(s_px, s_py, s_vx, s_vy, s_i, s_j,
                               sW1, sb1, sW2, sb2, sW3, s_b3, s_h1, s_h2, tid, &s_vmax);
                } else {
                    if (tid == 0) {
                        float pen = apply_wall1(s_px, s_py, s_vx, s_vy, s_i, s_j, s_r[s_i]);
                        s_disp += pen;
                    }
                    __syncthreads();
                }
            }
        }

        // -------- end-of-step final integration to t_e
        __syncthreads();
        if (tid == 0) {
            float dtef = (t_e > s_tc + 1e-10f) ? (t_e - s_tc) : 0.0f;
            g_dtef[step] = dtef;
            s_dte = dtef;
            s_disp = __fmaf_rn(s_vmax, dtef, s_disp);
        }
        __syncthreads();
        s_px[tid] = __fmaf_rn(s_vx[tid], s_dte, s_px[tid]);
        s_py[tid] = __fmaf_rn(s_vy[tid], s_dte, s_py[tid]);
        __syncthreads();
    }
}

// =============================== WORKERS =======================================
// One block per batch; replays the event log; writes all 101 output frames.
__global__ void __launch_bounds__(256, 1)
worker_kernel(const float* __restrict__ state, const float* __restrict__ radii,
              const float* __restrict__ W1, const float* __restrict__ b1,
              const float* __restrict__ W2, const float* __restrict__ b2,
              const float* __restrict__ W3, const float* __restrict__ b3,
              float* __restrict__ out)
{
    __shared__ float s_px[NBALLS], s_py[NBALLS], s_vx[NBALLS], s_vy[NBALLS], s_r[NBALLS];
    __shared__ float sW1[2 * HID], sb1[HID], sW2[HID * W2S], sb2[HID], sW3[HID];
    __shared__ float s_h1[HID], s_h2[HID];
    __shared__ float s_b3;
    __shared__ int   s_ty[MAXEV], s_ei[MAXEV], s_ej[MAXEV];
    __shared__ float s_dt[MAXEV], s_dtf;

    int tid = threadIdx.x;
    int b   = blockIdx.x;

    {
        float4 v = ((const float4*)(state + b * NBALLS * 4))[tid];
        s_px[tid] = v.x; s_py[tid] = v.y; s_vx[tid] = v.z; s_vy[tid] = v.w;
        s_r[tid] = radii[tid];
        ((float4*)out)[(size_t)b * NBALLS + tid] = v;    // frame 0 = initial state
    }
    if (tid < 2 * HID) sW1[tid] = W1[tid];
    if (tid < HID) { sb1[tid] = b1[tid]; sb2[tid] = b2[tid]; sW3[tid] = W3[tid]; }
    for (int t = tid; t < HID * HID; t += 256) sW2[(t >> 6) * W2S + (t & 63)] = W2[t];
    if (tid == 0) s_b3 = b3[0];
    __syncthreads();

    for (int step = 0; step < NSTEPS; step++) {
        int base = step * MAXEV;
        if (tid < MAXEV) {
            s_ty[tid] = g_type[base + tid];
            s_ei[tid] = g_ei[base + tid];
            s_ej[tid] = g_ej[base + tid];
            s_dt[tid] = g_dte[base + tid];
        }
        if (tid == MAXEV) s_dtf = g_dtef[step];
        __syncthreads();

        for (int e = 0; e < MAXEV; e++) {
            int ty = s_ty[e];
            if (ty == 0) continue;
            if (ty == 2 || ty == 4) {
                s_px[tid] = __fmaf_rn(s_vx[tid], s_dt[e], s_px[tid]);
                s_py[tid] = __fmaf_rn(s_vy[tid], s_dt[e], s_py[tid]);
                __syncthreads();
            }
            if (ty <= 2) {
                apply_jump(s_px, s_py, s_vx, s_vy, s_ei[e], s_ej[e],
                           sW1, sb1, sW2, sb2, sW3, s_b3, s_h1, s_h2, tid, nullptr);
            } else {
                if (tid == 0) apply_wall1(s_px, s_py, s_vx, s_vy, s_ei[e], s_ej[e], s_r[s_ei[e]]);
                __syncthreads();
            }
        }

        // final integration to t_e and frame write
        s_px[tid] = __fmaf_rn(s_vx[tid], s_dtf, s_px[tid]);
        s_py[tid] = __fmaf_rn(s_vy[tid], s_dtf, s_py[tid]);
        __syncthreads();
        float4 v = make_float4(s_px[tid], s_py[tid], s_vx[tid], s_vy[tid]);
        ((float4*)out)[((size_t)(step + 1) * BATCHN + b) * NBALLS + tid] = v;
        __syncthreads();   // protect s_ty reload next step
    }
}

// =============================== LAUNCH ========================================
extern "C" void kernel_launch(void* const* d_in, const int* in_sizes, int n_in,
                              void* d_out, int out_size)
{
    const float* state = (const float*)d_in[0];
    const float* radii = (const float*)d_in[1];
    const float* W1    = (const float*)d_in[2];
    const float* b1    = (const float*)d_in[3];
    const float* W2    = (const float*)d_in[4];
    const float* b2    = (const float*)d_in[5];
    const float* W3    = (const float*)d_in[6];
    const float* b3    = (const float*)d_in[7];
    float* out = (float*)d_out;

    sched_kernel<<<1, 256>>>(state, radii, W1, b1, W2, b2, W3, b3);
    worker_kernel<<<BATCHN, 256>>>(state, radii, W1, b1, W2, b2, W3, b3, out);
}

// round 8
// speedup vs baseline: 1.0253x; 1.0253x over previous
#include <cuda_runtime.h>
#include <math.h>

#define NBALLS  256
#define BATCHN  128
#define NSTEPS  100
#define MAXEV   5
#define HID     64
#define P_PAIRS 32640          // 256*255/2
#define DTCONST 0.05f
#define WORLDSZ 10.0f
#define W2S     65             // padded W2 row stride (conflict-free)
#define SLOTS   24             // candidate slots per ball (forward neighbors)

// ---------------- event log (device globals; no allocation) --------------------
__device__ int   g_type[NSTEPS * MAXEV];
__device__ int   g_ei  [NSTEPS * MAXEV];
__device__ int   g_ej  [NSTEPS * MAXEV];
__device__ float g_dte [NSTEPS * MAXEV];
__device__ float g_dtef[NSTEPS];

__constant__ float c_wnx[4] = { 1.f, -1.f, 0.f,  0.f };
__constant__ float c_wny[4] = { 0.f,  0.f, 1.f, -1.f };
__constant__ float c_wp [4] = { 0.f, -WORLDSZ, 0.f, -WORLDSZ };

__device__ __forceinline__ float silu_f(float x) {
    float s = 1.0f / (1.0f + expf(-x));
    return x * s;
}
__device__ __forceinline__ unsigned fkey(float f) {
    unsigned u = __float_as_uint(f);
    return (u & 0x80000000u) ? ~u : (u | 0x80000000u);
}
__device__ __forceinline__ float funkey(unsigned u) {
    u = (u & 0x80000000u) ? (u & 0x7FFFFFFFu) : ~u;
    return __uint_as_float(u);
}
__device__ __forceinline__ int triu_off(int i) {
    return i * 255 - ((i * (i - 1)) >> 1);
}

// ---------------- candidate evaluation (bit-identical to passing R1/R2) --------
__device__ __forceinline__ void eval_pair(int i, int j,
    const float* px, const float* py, const float* vx, const float* vy, const float* r,
    unsigned long long& bk, unsigned& ba)
{
    float dxp = px[j] - px[i];
    float dyp = py[j] - py[i];
    float d2  = __fmaf_rn(dxp, dxp, dyp * dyp);
    if (d2 <= 0.06255f) {                              // dist <= ~0.25 (+margin)
        float dist = sqrtf(d2);
        float den  = dist + 1e-8f;
        float ab   = __fmaf_rn(vx[j] - vx[i], dxp / den, (vy[j] - vy[i]) * (dyp / den));
        if (ab < 0.0f) {
            float gap = dist - (r[i] + r[j]);
            unsigned kk = (unsigned)(triu_off(i) + (j - i - 1));
            unsigned long long key = (((unsigned long long)fkey(gap)) << 32) | kk;
            if (key < bk) { bk = key; ba = (unsigned)i; }
        }
    }
}

// ---------------- apply routines (bit-identical math) --------------------------
__device__ void apply_jump(float* px, float* py, float* vx, float* vy,
                           int i, int j,
                           const float* sW1, const float* sb1,
                           const float* sW2, const float* sb2,
                           const float* sW3, float b3v,
                           float* h1, float* h2, int tid, float* vmax)
{
    float dx = px[j] - px[i];
    float dy = py[j] - py[i];
    float dist = sqrtf(__fmaf_rn(dx, dx, dy * dy));
    dist = fmaxf(dist, 1e-8f);
    float nhx = dx / dist, nhy = dy / dist;
    float app = __fmaf_rn(vx[j] - vx[i], nhx, (vy[j] - vy[i]) * nhy);

    if (tid < HID) {
        float z = __fmaf_rn(dist, sW1[2 * tid], __fmaf_rn(app, sW1[2 * tid + 1], sb1[tid]));
        h1[tid] = silu_f(z);
    }
    __syncthreads();
    if (tid < HID) {
        float acc = 0.0f;
        const float* row = sW2 + tid * W2S;            // padded stride: conflict-free
#pragma unroll 8
        for (int m = 0; m < HID; m++) acc = __fmaf_rn(row[m], h1[m], acc);
        h2[tid] = silu_f(acc + sb2[tid]);
    }
    __syncthreads();
    if (tid == 0) {
        float acc = 0.0f;
        for (int m = 0; m < HID; m++) acc = __fmaf_rn(sW3[m], h2[m], acc);
        float imp = acc + b3v;
        float ix = imp * nhx, iy = imp * nhy;
        vx[i] += ix; vy[i] += iy;
        vx[j] -= ix; vy[j] -= iy;
        if (vmax) *vmax += fabsf(imp);
    }
    __syncthreads();
}

__device__ __forceinline__ float apply_wall1(float* px, float* py, float* vx, float* vy,
                                             int i, int w, float r)
{
    float wnx = c_wnx[w], wny = c_wny[w], wpv = c_wp[w];
    float v0 = vx[i], v1 = vy[i], p0 = px[i], p1 = py[i];
    float vn = __fmaf_rn(v0, wnx, v1 * wny);
    float t2 = 2.0f * vn;
    vx[i] = v0 - t2 * wnx;
    vy[i] = v1 - t2 * wny;
    float pn  = __fmaf_rn(p0, wnx, p1 * wny);
    float pen = fmaxf((wpv + r) - pn, 0.0f);
    px[i] = __fmaf_rn(pen, wnx, p0);
    py[i] = __fmaf_rn(pen, wny, p1);
    return pen;
}

// =============================== SCHEDULER =====================================
// One 256-thread block simulates batch 0 and emits the global event log.
// Atomic-free slot-based candidate lists; displacement-tracked safe rebuilds.
__global__ void __launch_bounds__(256, 1)
sched_kernel(const float* __restrict__ state, const float* __restrict__ radii,
             const float* __restrict__ W1, const float* __restrict__ b1,
             const float* __restrict__ W2, const float* __restrict__ b2,
             const float* __restrict__ W3, const float* __restrict__ b3)
{
    __shared__ float s_px[NBALLS], s_py[NBALLS], s_vx[NBALLS], s_vy[NBALLS], s_r[NBALLS];
    __shared__ float sW1[2 * HID], sb1[HID], sW2[HID * W2S], sb2[HID], sW3[HID];
    __shared__ float s_h1[HID], s_h2[HID];
    __shared__ unsigned long long red_k[8];
    __shared__ unsigned red_a[8];
    __shared__ float red_f[8];
    __shared__ int s_type, s_i, s_j, s_done, s_over;
    __shared__ float s_dte, s_tc, s_b3, s_disp, s_vmax;
    __shared__ unsigned short cand[SLOTS * NBALLS];    // [k*256 + ball], sentinel 0xFFFF

    const int tid  = threadIdx.x;
    const int warp = tid >> 5, lane = tid & 31;

    {   // load state: tid == ball
        float4 v = ((const float4*)state)[tid];        // batch 0 = first 256 float4s
        s_px[tid] = v.x; s_py[tid] = v.y; s_vx[tid] = v.z; s_vy[tid] = v.w;
        s_r[tid] = radii[tid];
    }
    if (tid < 2 * HID) sW1[tid] = W1[tid];
    if (tid < HID) { sb1[tid] = b1[tid]; sb2[tid] = b2[tid]; sW3[tid] = W3[tid]; }
    for (int t = tid; t < HID * HID; t += 256) sW2[(t >> 6) * W2S + (t & 63)] = W2[t];
    if (tid == 0) { s_b3 = b3[0]; s_disp = 1e30f; s_vmax = 0.f; s_over = 0; }
    __syncthreads();

    for (int step = 0; step < NSTEPS; step++) {
        float t_s = (float)step * DTCONST;
        float t_e = t_s + DTCONST;
        if (tid == 0) {
            s_tc = t_s; s_done = 0;
#pragma unroll
            for (int e = 0; e < MAXEV; e++) g_type[step * MAXEV + e] = 0;
        }
        __syncthreads();

        for (int ev = 0; ev < MAXEV; ev++) {
            if (s_done) break;

            // ---- atomic-free rebuild when displacement bound erodes margin ----
            // Safety: pair absent from list => dist > 1.25 at build; until any two
            // balls move 2*0.49 < 1.0, dist stays > 0.25 => cannot pass eval gate.
            if (s_disp > 0.49f) {
                if (tid == 0) s_over = 0;
                __syncthreads();
                float bx = s_px[tid], by = s_py[tid];
                int cnt = 0;
#pragma unroll 4
                for (int d = 1; d <= 128; d++) {
                    if (d == 128 && tid >= 128) break;
                    int o = tid + d; if (o >= 256) o -= 256;
                    float dx = s_px[o] - bx;
                    if (fabsf(dx) < 1.2502f) {
                        float dy = s_py[o] - by;
                        if (__fmaf_rn(dx, dx, dy * dy) <= 1.5635f) {   // dist <= 1.25
                            int i, j;
                            if (o > tid) { i = tid; j = o; } else { i = o; j = tid; }
                            if (cnt < SLOTS) cand[cnt * NBALLS + tid] = (unsigned short)((i << 8) | j);
                            else s_over = 1;
                            cnt++;
                        }
                    }
                }
                for (int k = (cnt < SLOTS ? cnt : SLOTS); k < SLOTS; k++)
                    cand[k * NBALLS + tid] = 0xFFFFu;
                // vmax = max ball speed (displacement rate bound)
                float sp = sqrtf(__fmaf_rn(s_vx[tid], s_vx[tid], s_vy[tid] * s_vy[tid]));
#pragma unroll
                for (int off = 16; off; off >>= 1)
                    sp = fmaxf(sp, __shfl_down_sync(0xffffffffu, sp, off));
                if (lane == 0) red_f[warp] = sp;
                __syncthreads();
                if (tid == 0) {
                    float m = red_f[0];
#pragma unroll
                    for (int k = 1; k < 8; k++) m = fmaxf(m, red_f[k]);
                    s_vmax = m;
                    s_disp = 0.0f;
                }
                __syncthreads();
            }

            // ---- detection: inline walls (ball = tid) + own slot list ----
            unsigned long long bk = ~0ull;
            unsigned ba = 0u;
            {
                float bx = s_px[tid], by = s_py[tid];
                float vx0 = s_vx[tid], vy0 = s_vy[tid], rr = s_r[tid];
                float g[4];
                g[0] = bx - rr;
                g[1] = (WORLDSZ - bx) - rr;
                g[2] = by - rr;
                g[3] = (WORLDSZ - by) - rr;
                bool a[4] = { vx0 < 0.f, vx0 > 0.f, vy0 < 0.f, vy0 > 0.f };
                unsigned kb = (unsigned)(P_PAIRS + tid * 4);
#pragma unroll
                for (int w = 0; w < 4; w++) {
                    if (a[w]) {
                        unsigned long long key = (((unsigned long long)fkey(g[w])) << 32) | (kb + w);
                        if (key < bk) bk = key;
                    }
                }
            }
            if (!s_over) {
                for (int k = 0; k < SLOTS; k++) {
                    unsigned pk = cand[k * NBALLS + tid];
                    if (pk == 0xFFFFu) break;              // slots filled in order
                    eval_pair(pk >> 8, pk & 255, s_px, s_py, s_vx, s_vy, s_r, bk, ba);
                }
            } else {
                // exact full-scan fallback
                float bx = s_px[tid];
                for (int d = 1; d <= 128; d++) {
                    if (d == 128 && tid >= 128) break;
                    int o = tid + d; if (o >= 256) o -= 256;
                    float dx = s_px[o] - bx;
                    if (fabsf(dx) < 0.2502f) {
                        int i, j;
                        if (o > tid) { i = tid; j = o; } else { i = o; j = tid; }
                        eval_pair(i, j, s_px, s_py, s_vx, s_vy, s_r, bk, ba);
                    }
                }
            }

            // ---- argmin reduction; low-bits index => first-index tie-break ----
#pragma unroll
            for (int off = 16; off; off >>= 1) {
                unsigned long long ok = __shfl_down_sync(0xffffffffu, bk, off);
                unsigned oa = __shfl_down_sync(0xffffffffu, ba, off);
                if (ok < bk) { bk = ok; ba = oa; }
            }
            if (lane == 0) { red_k[warp] = bk; red_a[warp] = ba; }
            __syncthreads();
            if (tid == 0) {
                bk = red_k[0]; ba = red_a[0];
#pragma unroll
                for (int k = 1; k < 8; k++)
                    if (red_k[k] < bk) { bk = red_k[k]; ba = red_a[k]; }

                // ---- scalar event decision (bit-identical to R1) ----
                int type = 0, ei = 0, ej = 0;
                float dte = 0.0f;
                if (bk != ~0ull) {
                    unsigned k = (unsigned)bk;
                    float gap = funkey((unsigned)(bk >> 32));
                    if (gap <= 0.05f) {
                        bool isball = (k < P_PAIRS);
                        float app;
                        if (isball) {
                            ei = (int)ba;
                            ej = (int)k - triu_off(ei) + ei + 1;
                            float nx = s_px[ej] - s_px[ei];
                            float ny = s_py[ej] - s_py[ei];
                            float nn = sqrtf(__fmaf_rn(nx, nx, ny * ny));
                            float ax = ((s_vx[ej] - s_vx[ei]) * nx) / nn;
                            float ay = ((s_vy[ej] - s_vy[ei]) * ny) / nn;
                            app = -(ax + ay);
                        } else {
                            int kw = (int)k - P_PAIRS;
                            ei = kw >> 2; ej = kw & 3;
                            app = fabsf(fmaxf(s_vx[ei], s_vy[ei]));
                        }
                        float t_ev = s_tc + gap / fmaxf(app, 1e-6f);
                        if (gap <= 0.0f) {
                            type = isball ? 1 : 3;          // case_a
                            dte = 0.0f;
                        } else if (app > 1e-6f && t_ev < t_e) {
                            type = isball ? 2 : 4;          // case_b
                            dte = (t_ev > s_tc + 1e-10f) ? (t_ev - s_tc) : 0.0f;
                            s_tc = t_ev;
                            s_disp = __fmaf_rn(s_vmax, dte, s_disp);
                        } else s_done = 1;
                    } else s_done = 1;
                } else s_done = 1;
                s_type = type; s_i = ei; s_j = ej; s_dte = dte;
                int idx = step * MAXEV + ev;
                g_type[idx] = type; g_ei[idx] = ei; g_ej[idx] = ej; g_dte[idx] = dte;
            }
            __syncthreads();

            // ---- apply to batch-0 state ----
            int ty = s_type;
            if (ty != 0) {
                if (ty == 2 || ty == 4) {
                    s_px[tid] = __fmaf_rn(s_vx[tid], s_dte, s_px[tid]);
                    s_py[tid] = __fmaf_rn(s_vy[tid], s_dte, s_py[tid]);
                    __syncthreads();
                }
                if (ty <= 2) {
                    apply_jump(s_px, s_py, s_vx, s_vy, s_i, s_j,
                               sW1, sb1, sW2, sb2, sW3, s_b3, s_h1, s_h2, tid, &s_vmax);
                } else {
                    if (tid == 0) s_disp += apply_wall1(s_px, s_py, s_vx, s_vy, s_i, s_j, s_r[s_i]);
                    __syncthreads();
                }
            }
        }

        // ---- end-of-step final integration to t_e ----
        __syncthreads();
        if (tid == 0) {
            float dtef = (t_e > s_tc + 1e-10f) ? (t_e - s_tc) : 0.0f;
            g_dtef[step] = dtef;
            s_dte = dtef;
            s_disp = __fmaf_rn(s_vmax, dtef, s_disp);
        }
        __syncthreads();
        s_px[tid] = __fmaf_rn(s_vx[tid], s_dte, s_px[tid]);
        s_py[tid] = __fmaf_rn(s_vy[tid], s_dte, s_py[tid]);
        __syncthreads();
    }
}

// =============================== WORKERS =======================================
// One block per batch; replays the event log; writes all 101 output frames.
__global__ void __launch_bounds__(256, 1)
worker_kernel(const float* __restrict__ state, const float* __restrict__ radii,
              const float* __restrict__ W1, const float* __restrict__ b1,
              const float* __restrict__ W2, const float* __restrict__ b2,
              const float* __restrict__ W3, const float* __restrict__ b3,
              float* __restrict__ out)
{
    __shared__ float s_px[NBALLS], s_py[NBALLS], s_vx[NBALLS], s_vy[NBALLS], s_r[NBALLS];
    __shared__ float sW1[2 * HID], sb1[HID], sW2[HID * W2S], sb2[HID], sW3[HID];
    __shared__ float s_h1[HID], s_h2[HID];
    __shared__ float s_b3;
    __shared__ int   s_ty[MAXEV], s_ei[MAXEV], s_ej[MAXEV];
    __shared__ float s_dt[MAXEV], s_dtf;

    int tid = threadIdx.x;
    int b   = blockIdx.x;

    {
        float4 v = ((const float4*)(state + b * NBALLS * 4))[tid];
        s_px[tid] = v.x; s_py[tid] = v.y; s_vx[tid] = v.z; s_vy[tid] = v.w;
        s_r[tid] = radii[tid];
        ((float4*)out)[(size_t)b * NBALLS + tid] = v;    // frame 0 = initial state
    }
    if (tid < 2 * HID) sW1[tid] = W1[tid];
    if (tid < HID) { sb1[tid] = b1[tid]; sb2[tid] = b2[tid]; sW3[tid] = W3[tid]; }
    for (int t = tid; t < HID * HID; t += 256) sW2[(t >> 6) * W2S + (t & 63)] = W2[t];
    if (tid == 0) s_b3 = b3[0];
    __syncthreads();

    for (int step = 0; step < NSTEPS; step++) {
        int base = step * MAXEV;
        if (tid < MAXEV) {
            s_ty[tid] = g_type[base + tid];
            s_ei[tid] = g_ei[base + tid];
            s_ej[tid] = g_ej[base + tid];
            s_dt[tid] = g_dte[base + tid];
        }
        if (tid == MAXEV) s_dtf = g_dtef[step];
        __syncthreads();

        for (int e = 0; e < MAXEV; e++) {
            int ty = s_ty[e];
            if (ty == 0) continue;
            if (ty == 2 || ty == 4) {
                s_px[tid] = __fmaf_rn(s_vx[tid], s_dt[e], s_px[tid]);
                s_py[tid] = __fmaf_rn(s_vy[tid], s_dt[e], s_py[tid]);
                __syncthreads();
            }
            if (ty <= 2) {
                apply_jump(s_px, s_py, s_vx, s_vy, s_ei[e], s_ej[e],
                           sW1, sb1, sW2, sb2, sW3, s_b3, s_h1, s_h2, tid, nullptr);
            } else {
                if (tid == 0) apply_wall1(s_px, s_py, s_vx, s_vy, s_ei[e], s_ej[e], s_r[s_ei[e]]);
                __syncthreads();
            }
        }

        // final integration to t_e and frame write
        s_px[tid] = __fmaf_rn(s_vx[tid], s_dtf, s_px[tid]);
        s_py[tid] = __fmaf_rn(s_vy[tid], s_dtf, s_py[tid]);
        __syncthreads();
        float4 v = make_float4(s_px[tid], s_py[tid], s_vx[tid], s_vy[tid]);
        ((float4*)out)[((size_t)(step + 1) * BATCHN + b) * NBALLS + tid] = v;
        __syncthreads();   // protect s_ty reload next step
    }
}

// =============================== LAUNCH ========================================
extern "C" void kernel_launch(void* const* d_in, const int* in_sizes, int n_in,
                              void* d_out, int out_size)
{
    const float* state = (const float*)d_in[0];
    const float* radii = (const float*)d_in[1];
    const float* W1    = (const float*)d_in[2];
    const float* b1    = (const float*)d_in[3];
    const float* W2    = (const float*)d_in[4];
    const float* b2    = (const float*)d_in[5];
    const float* W3    = (const float*)d_in[6];
    const float* b3    = (const float*)d_in[7];
    float* out = (float*)d_out;

    sched_kernel<<<1, 256>>>(state, radii, W1, b1, W2, b2, W3, b3);
    worker_kernel<<<BATCHN, 256>>>(state, radii, W1, b1, W2, b2, W3, b3, out);
}

// round 13
// speedup vs baseline: 1.2121x; 1.1822x over previous
#include <cuda_runtime.h>
#include <math.h>

#define NBALLS  256
#define BATCHN  128
#define NSTEPS  100
#define MAXEV   5
#define HID     64
#define P_PAIRS 32640          // 256*255/2
#define DTCONST 0.05f
#define WORLDSZ 10.0f
#define W2S     65             // padded W2 row stride (conflict-free)
#define SLOTS   24             // candidate slots per ball (forward neighbors)
#define WAIT_CAP 20000000      // bounded spin: impossible to hit unless logic bug

// ---------------- event log + publish flag (device globals) --------------------
__device__ int   g_type[NSTEPS * MAXEV];
__device__ int   g_ei  [NSTEPS * MAXEV];
__device__ int   g_ej  [NSTEPS * MAXEV];
__device__ float g_dte [NSTEPS * MAXEV];
__device__ float g_dtef[NSTEPS];
__device__ int   g_publish;            // #completed steps; reset each launch

__constant__ float c_wnx[4] = { 1.f, -1.f, 0.f,  0.f };
__constant__ float c_wny[4] = { 0.f,  0.f, 1.f, -1.f };
__constant__ float c_wp [4] = { 0.f, -WORLDSZ, 0.f, -WORLDSZ };

// ---------------- dynamic shared-memory layout ---------------------------------
struct Smem {
    float px[NBALLS], py[NBALLS], vx[NBALLS], vy[NBALLS], r[NBALLS];
    float W1[2 * HID], b1[HID], W2[HID * W2S], b2[HID], W3v[HID];
    float h1[HID], h2[HID];
    unsigned long long red_k[8];
    unsigned red_a[8];
    float red_f[8];
    int  type, ei, ej, done, over;
    float dte, tc, b3v, disp, vmax;
    int   ty[MAXEV], eei[MAXEV], eej[MAXEV];
    float edt[MAXEV], dtf;
    unsigned short cand[SLOTS * NBALLS];   // sched only; [k*256 + ball]
};

__device__ __forceinline__ float silu_f(float x) {
    float s = 1.0f / (1.0f + expf(-x));
    return x * s;
}
__device__ __forceinline__ unsigned fkey(float f) {
    unsigned u = __float_as_uint(f);
    return (u & 0x80000000u) ? ~u : (u | 0x80000000u);
}
__device__ __forceinline__ float funkey(unsigned u) {
    u = (u & 0x80000000u) ? (u & 0x7FFFFFFFu) : ~u;
    return __uint_as_float(u);
}
__device__ __forceinline__ int triu_off(int i) {
    return i * 255 - ((i * (i - 1)) >> 1);
}

// ---------------- candidate evaluation (bit-identical to passing R1/R8) --------
__device__ __forceinline__ void eval_pair(int i, int j, const Smem& s,
                                          unsigned long long& bk, unsigned& ba)
{
    float dxp = s.px[j] - s.px[i];
    float dyp = s.py[j] - s.py[i];
    float d2  = __fmaf_rn(dxp, dxp, dyp * dyp);
    if (d2 <= 0.06255f) {
        float dist = sqrtf(d2);
        float den  = dist + 1e-8f;
        float ab   = __fmaf_rn(s.vx[j] - s.vx[i], dxp / den, (s.vy[j] - s.vy[i]) * (dyp / den));
        if (ab < 0.0f) {
            float gap = dist - (s.r[i] + s.r[j]);
            unsigned kk = (unsigned)(triu_off(i) + (j - i - 1));
            unsigned long long key = (((unsigned long long)fkey(gap)) << 32) | kk;
            if (key < bk) { bk = key; ba = (unsigned)i; }
        }
    }
}

// ---------------- apply routines (bit-identical math) --------------------------
__device__ void apply_jump(Smem& s, int i, int j, int tid, bool track)
{
    float dx = s.px[j] - s.px[i];
    float dy = s.py[j] - s.py[i];
    float dist = sqrtf(__fmaf_rn(dx, dx, dy * dy));
    dist = fmaxf(dist, 1e-8f);
    float nhx = dx / dist, nhy = dy / dist;
    float app = __fmaf_rn(s.vx[j] - s.vx[i], nhx, (s.vy[j] - s.vy[i]) * nhy);

    if (tid < HID) {
        float z = __fmaf_rn(dist, s.W1[2 * tid], __fmaf_rn(app, s.W1[2 * tid + 1], s.b1[tid]));
        s.h1[tid] = silu_f(z);
    }
    __syncthreads();
    if (tid < HID) {
        float acc = 0.0f;
        const float* row = s.W2 + tid * W2S;           // padded stride: conflict-free
#pragma unroll 8
        for (int m = 0; m < HID; m++) acc = __fmaf_rn(row[m], s.h1[m], acc);
        s.h2[tid] = silu_f(acc + s.b2[tid]);
    }
    __syncthreads();
    if (tid == 0) {
        float acc = 0.0f;
        for (int m = 0; m < HID; m++) acc = __fmaf_rn(s.W3v[m], s.h2[m], acc);
        float imp = acc + s.b3v;
        float ix = imp * nhx, iy = imp * nhy;
        s.vx[i] += ix; s.vy[i] += iy;
        s.vx[j] -= ix; s.vy[j] -= iy;
        if (track) s.vmax += fabsf(imp);
    }
    __syncthreads();
}

__device__ __forceinline__ float apply_wall1(Smem& s, int i, int w)
{
    float r = s.r[i];
    float wnx = c_wnx[w], wny = c_wny[w], wpv = c_wp[w];
    float v0 = s.vx[i], v1 = s.vy[i], p0 = s.px[i], p1 = s.py[i];
    float vn = __fmaf_rn(v0, wnx, v1 * wny);
    float t2 = 2.0f * vn;
    s.vx[i] = v0 - t2 * wnx;
    s.vy[i] = v1 - t2 * wny;
    float pn  = __fmaf_rn(p0, wnx, p1 * wny);
    float pen = fmaxf((wpv + r) - pn, 0.0f);
    s.px[i] = __fmaf_rn(pen, wnx, p0);
    s.py[i] = __fmaf_rn(pen, wny, p1);
    return pen;
}

// ---------------- common loads -------------------------------------------------
__device__ void load_common(Smem& s, int tid, int batch,
    const float* state, const float* radii,
    const float* W1, const float* b1, const float* W2, const float* b2,
    const float* W3, const float* b3)
{
    float4 v = ((const float4*)(state + batch * NBALLS * 4))[tid];
    s.px[tid] = v.x; s.py[tid] = v.y; s.vx[tid] = v.z; s.vy[tid] = v.w;
    s.r[tid] = radii[tid];
    if (tid < 2 * HID) s.W1[tid] = W1[tid];
    if (tid < HID) { s.b1[tid] = b1[tid]; s.b2[tid] = b2[tid]; s.W3v[tid] = W3[tid]; }
    for (int t = tid; t < HID * HID; t += 256) s.W2[(t >> 6) * W2S + (t & 63)] = W2[t];
    if (tid == 0) s.b3v = b3[0];
}

// =============================== SCHEDULER BODY ================================
// Exact port of the PASSING R8 scheduler (bit-identical math), plus per-step
// publish of the event log for the in-flight worker blocks.
__device__ void sched_body(Smem& s, int tid)
{
    const int warp = tid >> 5, lane = tid & 31;
    if (tid == 0) { s.disp = 1e30f; s.vmax = 0.f; s.over = 0; }
    __syncthreads();

    for (int step = 0; step < NSTEPS; step++) {
        float t_s = (float)step * DTCONST;
        float t_e = t_s + DTCONST;
        if (tid == 0) {
            s.tc = t_s; s.done = 0;
#pragma unroll
            for (int e = 0; e < MAXEV; e++) g_type[step * MAXEV + e] = 0;
        }
        __syncthreads();

        for (int ev = 0; ev < MAXEV; ev++) {
            if (s.done) break;

            // ---- atomic-free rebuild when displacement bound erodes margin ----
            // Safety: pair absent => dist > 1.25 at build; until two balls each
            // move 0.49 (2*0.49 < 1.0), dist stays > 0.25 => cannot pass gate.
            if (s.disp > 0.49f) {
                if (tid == 0) s.over = 0;
                __syncthreads();
                float bx = s.px[tid], by = s.py[tid];
                int cnt = 0;
#pragma unroll 4
                for (int d = 1; d <= 128; d++) {
                    if (d == 128 && tid >= 128) break;
                    int o = tid + d; if (o >= 256) o -= 256;
                    float dx = s.px[o] - bx;
                    if (fabsf(dx) < 1.2502f) {
                        float dy = s.py[o] - by;
                        if (__fmaf_rn(dx, dx, dy * dy) <= 1.5635f) {   // dist <= 1.25
                            int i, j;
                            if (o > tid) { i = tid; j = o; } else { i = o; j = tid; }
                            if (cnt < SLOTS) s.cand[cnt * NBALLS + tid] = (unsigned short)((i << 8) | j);
                            else s.over = 1;
                            cnt++;
                        }
                    }
                }
                for (int k = (cnt < SLOTS ? cnt : SLOTS); k < SLOTS; k++)
                    s.cand[k * NBALLS + tid] = 0xFFFFu;
                float sp = sqrtf(__fmaf_rn(s.vx[tid], s.vx[tid], s.vy[tid] * s.vy[tid]));
#pragma unroll
                for (int off = 16; off; off >>= 1)
                    sp = fmaxf(sp, __shfl_down_sync(0xffffffffu, sp, off));
                if (lane == 0) s.red_f[warp] = sp;
                __syncthreads();
                if (tid == 0) {
                    float m = s.red_f[0];
#pragma unroll
                    for (int k = 1; k < 8; k++) m = fmaxf(m, s.red_f[k]);
                    s.vmax = m;
                    s.disp = 0.0f;
                }
                __syncthreads();
            }

            // ---- detection: inline walls (ball = tid) + own slot list ----
            unsigned long long bk = ~0ull;
            unsigned ba = 0u;
            {
                float bx = s.px[tid], by = s.py[tid];
                float vx0 = s.vx[tid], vy0 = s.vy[tid], rr = s.r[tid];
                float g[4];
                g[0] = bx - rr;
                g[1] = (WORLDSZ - bx) - rr;
                g[2] = by - rr;
                g[3] = (WORLDSZ - by) - rr;
                bool a[4] = { vx0 < 0.f, vx0 > 0.f, vy0 < 0.f, vy0 > 0.f };
                unsigned kb = (unsigned)(P_PAIRS + tid * 4);
#pragma unroll
                for (int w = 0; w < 4; w++) {
                    if (a[w]) {
                        unsigned long long key = (((unsigned long long)fkey(g[w])) << 32) | (kb + w);
                        if (key < bk) bk = key;
                    }
                }
            }
            if (!s.over) {
                for (int k = 0; k < SLOTS; k++) {
                    unsigned pk = s.cand[k * NBALLS + tid];
                    if (pk == 0xFFFFu) break;
                    eval_pair(pk >> 8, pk & 255, s, bk, ba);
                }
            } else {
                float bx = s.px[tid];
                for (int d = 1; d <= 128; d++) {
                    if (d == 128 && tid >= 128) break;
                    int o = tid + d; if (o >= 256) o -= 256;
                    float dx = s.px[o] - bx;
                    if (fabsf(dx) < 0.2502f) {
                        int i, j;
                        if (o > tid) { i = tid; j = o; } else { i = o; j = tid; }
                        eval_pair(i, j, s, bk, ba);
                    }
                }
            }

            // ---- argmin reduction; low-bits index => first-index tie-break ----
#pragma unroll
            for (int off = 16; off; off >>= 1) {
                unsigned long long ok = __shfl_down_sync(0xffffffffu, bk, off);
                unsigned oa = __shfl_down_sync(0xffffffffu, ba, off);
                if (ok < bk) { bk = ok; ba = oa; }
            }
            if (lane == 0) { s.red_k[warp] = bk; s.red_a[warp] = ba; }
            __syncthreads();
            if (tid == 0) {
                bk = s.red_k[0]; ba = s.red_a[0];
#pragma unroll
                for (int k = 1; k < 8; k++)
                    if (s.red_k[k] < bk) { bk = s.red_k[k]; ba = s.red_a[k]; }

                int type = 0, ei = 0, ej = 0;
                float dte = 0.0f;
                if (bk != ~0ull) {
                    unsigned k = (unsigned)bk;
                    float gap = funkey((unsigned)(bk >> 32));
                    if (gap <= 0.05f) {
                        bool isball = (k < P_PAIRS);
                        float app;
                        if (isball) {
                            ei = (int)ba;
                            ej = (int)k - triu_off(ei) + ei + 1;
                            float nx = s.px[ej] - s.px[ei];
                            float ny = s.py[ej] - s.py[ei];
                            float nn = sqrtf(__fmaf_rn(nx, nx, ny * ny));
                            float ax = ((s.vx[ej] - s.vx[ei]) * nx) / nn;
                            float ay = ((s.vy[ej] - s.vy[ei]) * ny) / nn;
                            app = -(ax + ay);
                        } else {
                            int kw = (int)k - P_PAIRS;
                            ei = kw >> 2; ej = kw & 3;
                            app = fabsf(fmaxf(s.vx[ei], s.vy[ei]));
                        }
                        float t_ev = s.tc + gap / fmaxf(app, 1e-6f);
                        if (gap <= 0.0f) {
                            type = isball ? 1 : 3;
                            dte = 0.0f;
                        } else if (app > 1e-6f && t_ev < t_e) {
                            type = isball ? 2 : 4;
                            dte = (t_ev > s.tc + 1e-10f) ? (t_ev - s.tc) : 0.0f;
                            s.tc = t_ev;
                            s.disp = __fmaf_rn(s.vmax, dte, s.disp);
                        } else s.done = 1;
                    } else s.done = 1;
                } else s.done = 1;
                s.type = type; s.ei = ei; s.ej = ej; s.dte = dte;
                int idx = step * MAXEV + ev;
                g_type[idx] = type; g_ei[idx] = ei; g_ej[idx] = ej; g_dte[idx] = dte;
            }
            __syncthreads();

            // ---- apply to batch-0 state ----
            int ty = s.type;
            if (ty != 0) {
                if (ty == 2 || ty == 4) {
                    s.px[tid] = __fmaf_rn(s.vx[tid], s.dte, s.px[tid]);
                    s.py[tid] = __fmaf_rn(s.vy[tid], s.dte, s.py[tid]);
                    __syncthreads();
                }
                if (ty <= 2) {
                    apply_jump(s, s.ei, s.ej, tid, true);
                } else {
                    if (tid == 0) s.disp += apply_wall1(s, s.ei, s.ej);
                    __syncthreads();
                }
            }
        }

        // ---- end-of-step: final dte, publish, integrate ----
        __syncthreads();
        if (tid == 0) {
            float dtef = (t_e > s.tc + 1e-10f) ? (t_e - s.tc) : 0.0f;
            g_dtef[step] = dtef;
            s.dte = dtef;
            s.disp = __fmaf_rn(s.vmax, dtef, s.disp);
            __threadfence();                               // release event log
            *((volatile int*)&g_publish) = step + 1;
        }
        __syncthreads();
        s.px[tid] = __fmaf_rn(s.vx[tid], s.dte, s.px[tid]);
        s.py[tid] = __fmaf_rn(s.vy[tid], s.dte, s.py[tid]);
        __syncthreads();
    }
}

// =============================== WORKER BODY ===================================
__device__ void worker_body(Smem& s, int tid, int b, float* out)
{
    {   // frame 0
        float4 v = make_float4(s.px[tid], s.py[tid], s.vx[tid], s.vy[tid]);
        ((float4*)out)[(size_t)b * NBALLS + tid] = v;
    }
    __syncthreads();

    for (int step = 0; step < NSTEPS; step++) {
        if (tid == 0) {
            // Bounded spin: normal wait is << 10 ms; cap => provably no hang.
            int it = 0;
            while (*((volatile int*)&g_publish) < step + 1) {
                __nanosleep(64);
                if (++it > WAIT_CAP) break;    // logic bug => visible rel_err, not a hang
            }
            __threadfence();                   // acquire
        }
        __syncthreads();

        int base = step * MAXEV;
        if (tid < MAXEV) {
            s.ty[tid]  = __ldcg(&g_type[base + tid]);
            s.eei[tid] = __ldcg(&g_ei[base + tid]);
            s.eej[tid] = __ldcg(&g_ej[base + tid]);
            s.edt[tid] = __ldcg(&g_dte[base + tid]);
        }
        if (tid == MAXEV) s.dtf = __ldcg(&g_dtef[step]);
        __syncthreads();

        for (int e = 0; e < MAXEV; e++) {
            int ty = s.ty[e];
            if (ty == 0) continue;
            if (ty == 2 || ty == 4) {
                s.px[tid] = __fmaf_rn(s.vx[tid], s.edt[e], s.px[tid]);
                s.py[tid] = __fmaf_rn(s.vy[tid], s.edt[e], s.py[tid]);
                __syncthreads();
            }
            if (ty <= 2) {
                apply_jump(s, s.eei[e], s.eej[e], tid, false);
            } else {
                if (tid == 0) apply_wall1(s, s.eei[e], s.eej[e]);
                __syncthreads();
            }
        }

        s.px[tid] = __fmaf_rn(s.vx[tid], s.dtf, s.px[tid]);
        s.py[tid] = __fmaf_rn(s.vy[tid], s.dtf, s.py[tid]);
        __syncthreads();
        float4 v = make_float4(s.px[tid], s.py[tid], s.vx[tid], s.vy[tid]);
        ((float4*)out)[((size_t)(step + 1) * BATCHN + b) * NBALLS + tid] = v;
        __syncthreads();
    }
}

// =============================== KERNELS =======================================
__global__ void reset_kernel() { g_publish = 0; }

__global__ void __launch_bounds__(256, 1)
fused_kernel(const float* __restrict__ state, const float* __restrict__ radii,
             const float* __restrict__ W1, const float* __restrict__ b1,
             const float* __restrict__ W2, const float* __restrict__ b2,
             const float* __restrict__ W3, const float* __restrict__ b3,
             float* __restrict__ out)
{
    extern __shared__ char dynsmem[];
    Smem& s = *reinterpret_cast<Smem*>(dynsmem);
    int tid = threadIdx.x;

    if (blockIdx.x == 0) {
        load_common(s, tid, 0, state, radii, W1, b1, W2, b2, W3, b3);
        __syncthreads();
        sched_body(s, tid);
    } else {
        int b = blockIdx.x - 1;
        load_common(s, tid, b, state, radii, W1, b1, W2, b2, W3, b3);
        __syncthreads();
        worker_body(s, tid, b, out);
    }
}

// =============================== LAUNCH ========================================
extern "C" void kernel_launch(void* const* d_in, const int* in_sizes, int n_in,
                              void* d_out, int out_size)
{
    const float* state = (const float*)d_in[0];
    const float* radii = (const float*)d_in[1];
    const float* W1    = (const float*)d_in[2];
    const float* b1    = (const float*)d_in[3];
    const float* W2    = (const float*)d_in[4];
    const float* b2    = (const float*)d_in[5];
    const float* W3    = (const float*)d_in[6];
    const float* b3    = (const float*)d_in[7];
    float* out = (float*)d_out;

    reset_kernel<<<1, 1>>>();
    fused_kernel<<<1 + BATCHN, 256, sizeof(Smem)>>>(state, radii, W1, b1, W2, b2, W3, b3, out);
}